// round 11
// baseline (speedup 1.0000x reference)
#include <cuda_runtime.h>
#include <cstdint>

// KV Q4 dequant, multi-tile CTAs with double-buffered TMA bulk stores:
//   - grid = 1024 CTAs (single wave), each CTA processes 4 tiles of 16KB output
//   - per tile: LDG loads -> dequant -> STS into buf[p] -> cp.async.bulk SMEM->global
//   - wait_group 1 keeps ONE bulk store in flight while computing the next tile,
//     overlapping the TMA drain with load/compute of the following tile
//   - nibble->float via exponent-bias trick (exact): f = as_float(0x4B000000|n) - 2^23
// Output layout: [ k_dequant flat | v_dequant flat ] (reference reshapes are views)

#define TILE_F4 1024   // float4 per tile = 16KB output, 8KB packed input
#define NTHREADS 256
#define GRID_CTAS 1024

__global__ __launch_bounds__(NTHREADS)
void kv_dequant_tma2(const int2* __restrict__ k_packed,
                     const float* __restrict__ k_scale,
                     const float* __restrict__ k_bias,
                     const int2* __restrict__ v_packed,
                     const float* __restrict__ v_scale,
                     const float* __restrict__ v_bias,
                     float4* __restrict__ out,
                     int tiles_per_tensor,     // 2048
                     int out_f4_per_tensor)    // 2,097,152
{
    __shared__ __align__(16) float4 buf[2][TILE_F4];

    int total_tiles = 2 * tiles_per_tensor;
    int j0 = threadIdx.x;
    const float C = 8388608.0f;  // 2^23

    int it = 0;
    for (int tile = blockIdx.x; tile < total_tiles; tile += gridDim.x, ++it) {
        int p = it & 1;

        // Before overwriting buf[p], make sure the bulk store issued 2 iters ago
        // (which reads buf[p]) has completed. Thread 0 owns the bulk_group.
        if (it >= 2) {
            if (j0 == 0)
                asm volatile("cp.async.bulk.wait_group.read 1;" ::: "memory");
            __syncthreads();
        }

        bool is_v = tile >= tiles_per_tensor;
        int t = is_v ? tile - tiles_per_tensor : tile;

        const int2*  src = is_v ? v_packed : k_packed;
        const float* sc  = is_v ? v_scale  : k_scale;
        const float* bi  = is_v ? v_bias   : k_bias;

        int base_f4 = t * TILE_F4;

        // Front-batched coalesced loads: 4x LDG.64 + scalar scale/bias
        int2 w[4];
        float s[4], b[4];
#pragma unroll
        for (int r = 0; r < 4; r++)
            w[r] = __ldg(&src[base_f4 + j0 + r * NTHREADS]);
#pragma unroll
        for (int r = 0; r < 4; r++) {
            int blk = (base_f4 + j0 + r * NTHREADS) >> 3;  // 8 float4 / quant block
            s[r] = __ldg(&sc[blk]);
            b[r] = __ldg(&bi[blk]);
        }

#pragma unroll
        for (int r = 0; r < 4; r++) {
            float4 o;
            o.x = (__int_as_float(0x4B000000 | (w[r].x & 15)) - C) * s[r] + b[r];
            o.y = (__int_as_float(0x4B000000 | (w[r].x >> 4)) - C) * s[r] + b[r];
            o.z = (__int_as_float(0x4B000000 | (w[r].y & 15)) - C) * s[r] + b[r];
            o.w = (__int_as_float(0x4B000000 | (w[r].y >> 4)) - C) * s[r] + b[r];
            buf[p][j0 + r * NTHREADS] = o;   // conflict-free contiguous STS.128
        }
        __syncthreads();

        if (j0 == 0) {
            uint32_t saddr = (uint32_t)__cvta_generic_to_shared(buf[p]);
            const float4* gdst = out + (is_v ? out_f4_per_tensor : 0) + base_f4;
            int nbytes = TILE_F4 * 16;
            asm volatile("fence.proxy.async.shared::cta;" ::: "memory");
            asm volatile(
                "cp.async.bulk.global.shared::cta.bulk_group [%0], [%1], %2;"
                :: "l"(gdst), "r"(saddr), "r"(nbytes) : "memory");
            asm volatile("cp.async.bulk.commit_group;" ::: "memory");
        }
    }

    // Drain all outstanding bulk stores before CTA exit (SMEM reads must finish).
    if (j0 == 0)
        asm volatile("cp.async.bulk.wait_group.read 0;" ::: "memory");
    __syncthreads();
}

extern "C" void kernel_launch(void* const* d_in, const int* in_sizes, int n_in,
                              void* d_out, int out_size)
{
    // metadata order: k_packed, k_scale, k_bias, v_packed, v_scale, v_bias, batch_size
    const int2*  k_packed = (const int2*) d_in[0];
    const float* k_scale  = (const float*)d_in[1];
    const float* k_bias   = (const float*)d_in[2];
    const int2*  v_packed = (const int2*) d_in[3];
    const float* v_scale  = (const float*)d_in[4];
    const float* v_bias   = (const float*)d_in[5];

    int n_packed_words    = in_sizes[0];                  // 4,194,304 words / tensor
    int out_f4_per_tensor = n_packed_words / 2;           // 2,097,152 float4 / tensor
    int tiles_per_tensor  = out_f4_per_tensor / TILE_F4;  // 2048

    kv_dequant_tma2<<<GRID_CTAS, NTHREADS>>>(k_packed, k_scale, k_bias,
                                             v_packed, v_scale, v_bias,
                                             (float4*)d_out,
                                             tiles_per_tensor, out_f4_per_tensor);
}

// round 14
// speedup vs baseline: 1.0541x; 1.0541x over previous
#include <cuda_runtime.h>
#include <cstdint>

// KV Q4 dequant, 2 tiles per CTA (one K + one V), fully front-batched:
//   - grid = 2048 CTAs; CTA t handles K-tile t and V-tile t (L2-die balance)
//   - ALL global loads (8x LDG.64 packed + 4x coalesced scale/bias into SMEM)
//     issued before any compute -> single latency wait, no intra-loop stalls
//   - two SMEM buffers, two cp.async.bulk stores; tile0's drain overlaps
//     tile1's compute; exit waits mostly on tile1's store only
//   - nibble->float via exponent-bias trick (exact)
// Output layout: [ k_dequant flat | v_dequant flat ] (reference reshapes are views)

#define TILE_F4 1024   // float4 per tile = 16KB output, 128 quant blocks
#define NTHREADS 256

__global__ __launch_bounds__(NTHREADS)
void kv_dequant_tma3(const int2* __restrict__ k_packed,
                     const float* __restrict__ k_scale,
                     const float* __restrict__ k_bias,
                     const int2* __restrict__ v_packed,
                     const float* __restrict__ v_scale,
                     const float* __restrict__ v_bias,
                     float4* __restrict__ out,
                     int out_f4_per_tensor)    // 2,097,152
{
    __shared__ __align__(16) float4 bufK[TILE_F4];
    __shared__ __align__(16) float4 bufV[TILE_F4];
    __shared__ float ksc[128], kbi[128], vsc[128], vbi[128];

    int t  = blockIdx.x;
    int j0 = threadIdx.x;
    int base_f4  = t * TILE_F4;      // float4 offset of tile in each tensor
    int blk_base = t * 128;          // quant-block offset (128 blocks / tile)

    // ---- Front-batch ALL global loads ----
    // Packed data: 4x LDG.64 per tensor, coalesced (warp covers 256B runs)
    int2 wk[4], wv[4];
#pragma unroll
    for (int r = 0; r < 4; r++) wk[r] = __ldg(&k_packed[base_f4 + j0 + r * NTHREADS]);
#pragma unroll
    for (int r = 0; r < 4; r++) wv[r] = __ldg(&v_packed[base_f4 + j0 + r * NTHREADS]);

    // Scale/bias staged via SMEM: 4 coalesced LDG.32 per thread (half-warp split)
    {
        int i = j0 & 127;
        if (j0 < 128) {
            ksc[i] = __ldg(&k_scale[blk_base + i]);
            vsc[i] = __ldg(&v_scale[blk_base + i]);
        } else {
            kbi[i] = __ldg(&k_bias[blk_base + i]);
            vbi[i] = __ldg(&v_bias[blk_base + i]);
        }
    }
    __syncthreads();   // scales/biases visible

    const float C = 8388608.0f;  // 2^23

    // ---- Tile 0: K ----
#pragma unroll
    for (int r = 0; r < 4; r++) {
        int f = j0 + r * NTHREADS;
        float s = ksc[f >> 3];
        float b = kbi[f >> 3];
        float4 o;
        o.x = (__int_as_float(0x4B000000 | (wk[r].x & 15)) - C) * s + b;
        o.y = (__int_as_float(0x4B000000 | (wk[r].x >> 4)) - C) * s + b;
        o.z = (__int_as_float(0x4B000000 | (wk[r].y & 15)) - C) * s + b;
        o.w = (__int_as_float(0x4B000000 | (wk[r].y >> 4)) - C) * s + b;
        bufK[f] = o;
    }
    __syncthreads();
    if (j0 == 0) {
        uint32_t saddr = (uint32_t)__cvta_generic_to_shared(bufK);
        const float4* gdst = out + base_f4;
        asm volatile("fence.proxy.async.shared::cta;" ::: "memory");
        asm volatile("cp.async.bulk.global.shared::cta.bulk_group [%0], [%1], %2;"
                     :: "l"(gdst), "r"(saddr), "n"(TILE_F4 * 16) : "memory");
        asm volatile("cp.async.bulk.commit_group;" ::: "memory");
    }

    // ---- Tile 1: V (compute overlaps K's bulk-store drain) ----
#pragma unroll
    for (int r = 0; r < 4; r++) {
        int f = j0 + r * NTHREADS;
        float s = vsc[f >> 3];
        float b = vbi[f >> 3];
        float4 o;
        o.x = (__int_as_float(0x4B000000 | (wv[r].x & 15)) - C) * s + b;
        o.y = (__int_as_float(0x4B000000 | (wv[r].x >> 4)) - C) * s + b;
        o.z = (__int_as_float(0x4B000000 | (wv[r].y & 15)) - C) * s + b;
        o.w = (__int_as_float(0x4B000000 | (wv[r].y >> 4)) - C) * s + b;
        bufV[f] = o;
    }
    __syncthreads();
    if (j0 == 0) {
        uint32_t saddr = (uint32_t)__cvta_generic_to_shared(bufV);
        const float4* gdst = out + out_f4_per_tensor + base_f4;
        asm volatile("fence.proxy.async.shared::cta;" ::: "memory");
        asm volatile("cp.async.bulk.global.shared::cta.bulk_group [%0], [%1], %2;"
                     :: "l"(gdst), "r"(saddr), "n"(TILE_F4 * 16) : "memory");
        asm volatile("cp.async.bulk.commit_group;" ::: "memory");
        // Drain before SMEM teardown (thread 0 holds the CTA open)
        asm volatile("cp.async.bulk.wait_group.read 0;" ::: "memory");
    }
}

extern "C" void kernel_launch(void* const* d_in, const int* in_sizes, int n_in,
                              void* d_out, int out_size)
{
    // metadata order: k_packed, k_scale, k_bias, v_packed, v_scale, v_bias, batch_size
    const int2*  k_packed = (const int2*) d_in[0];
    const float* k_scale  = (const float*)d_in[1];
    const float* k_bias   = (const float*)d_in[2];
    const int2*  v_packed = (const int2*) d_in[3];
    const float* v_scale  = (const float*)d_in[4];
    const float* v_bias   = (const float*)d_in[5];

    int n_packed_words    = in_sizes[0];                  // 4,194,304 words / tensor
    int out_f4_per_tensor = n_packed_words / 2;           // 2,097,152 float4 / tensor
    int tiles_per_tensor  = out_f4_per_tensor / TILE_F4;  // 2048 = grid

    kv_dequant_tma3<<<tiles_per_tensor, NTHREADS>>>(k_packed, k_scale, k_bias,
                                                    v_packed, v_scale, v_bias,
                                                    (float4*)d_out,
                                                    out_f4_per_tensor);
}